// round 13
// baseline (speedup 1.0000x reference)
#include <cuda_runtime.h>
#include <cuda_fp16.h>
#include <cstdint>

#define B_DIM   8192
#define IN_DIM  4096
#define OUT_DIM 4096

// ---------------- scratch (device globals; no allocations allowed) ----------------
__device__ float g_alpha[IN_DIM];
__device__ float g_delta[IN_DIM];
__device__ __half g_sT[(size_t)OUT_DIM * IN_DIM];   // sT[n][k] = s[k][n], fp16 {-1,0,1}
__device__ __half g_y[(size_t)B_DIM * IN_DIM];      // y = x * alpha, fp16

// ---------------- kernel 1: per-input-row delta & alpha ----------------
__global__ void stats_kernel(const float* __restrict__ w) {
    int i = blockIdx.x;
    const float* row = w + (size_t)i * OUT_DIM;
    int tid = threadIdx.x;

    float s = 0.f;
    for (int j = tid; j < OUT_DIM; j += 256) s += fabsf(row[j]);

    __shared__ float red[256];
    __shared__ float redc[256];
    red[tid] = s; __syncthreads();
    for (int k = 128; k > 0; k >>= 1) {
        if (tid < k) red[tid] += red[tid + k];
        __syncthreads();
    }
    __shared__ float deltaS;
    if (tid == 0) deltaS = (0.7f / OUT_DIM) * red[0];
    __syncthreads();
    float delta = deltaS;

    float cnt = 0.f, asum = 0.f;
    for (int j = tid; j < OUT_DIM; j += 256) {
        float a = fabsf(row[j]);
        if (a > delta) { cnt += 1.f; asum += a; }
    }
    red[tid] = asum; redc[tid] = cnt; __syncthreads();
    for (int k = 128; k > 0; k >>= 1) {
        if (tid < k) { red[tid] += red[tid + k]; redc[tid] += redc[tid + k]; }
        __syncthreads();
    }
    if (tid == 0) {
        g_delta[i] = delta;
        float c = redc[0];
        g_alpha[i] = (c > 0.f) ? red[0] / c : 0.f;
    }
}

// ---------------- kernel 2: ternarize + transpose to sT[n][k] (fp16) ----------------
__global__ void tern_kernel(const float* __restrict__ w) {
    __shared__ __half tile[32][33];
    int j = blockIdx.x * 32 + threadIdx.x;   // out dim (contiguous in w)
    int i = blockIdx.y * 32 + threadIdx.y;   // in dim
    float delta = g_delta[i];
    float v = w[(size_t)i * OUT_DIM + j];
    float s = (v > delta) ? 1.f : ((v < -delta) ? -1.f : 0.f);
    tile[threadIdx.y][threadIdx.x] = __float2half(s);
    __syncthreads();
    int jo = blockIdx.x * 32 + threadIdx.y;
    int io = blockIdx.y * 32 + threadIdx.x;
    g_sT[(size_t)jo * IN_DIM + io] = tile[threadIdx.x][threadIdx.y];
}

// ---------------- kernel 3: y = x*alpha -> fp16 ----------------
__global__ void scale_kernel(const float* __restrict__ x) {
    size_t idx4 = (size_t)blockIdx.x * 256 + threadIdx.x;
    size_t base = idx4 * 4;
    int col = (int)(base % IN_DIM);
    float4 xv = *(const float4*)(x + base);
    float4 av = *(const float4*)(g_alpha + col);
    __half2 h01 = __floats2half2_rn(xv.x * av.x, xv.y * av.y);
    __half2 h23 = __floats2half2_rn(xv.z * av.z, xv.w * av.w);
    __half2* py = (__half2*)(g_y + base);
    py[0] = h01; py[1] = h23;
}

// ---------------- kernel 4: GEMM out = y@sT' + bias ----------------
// CTA 128x256, warp 64x64 (2x4 warps), BK=32, 4-stage cp.async
#define BM 128
#define BN 256
#define BKT 32
#define LDSP 40                          // halves per smem row (32 + 8 pad)
#define A_ST (128 * LDSP)                // 5120 halves
#define B_ST (256 * LDSP)                // 10240 halves
#define NSTG 4
#define SMEM_BYTES ((NSTG * (A_ST + B_ST)) * 2)   // 122880 B

__device__ __forceinline__ uint32_t smem_u32(const void* p) {
    uint32_t a;
    asm("{ .reg .u64 t; cvta.to.shared.u64 t, %1; cvt.u32.u64 %0, t; }" : "=r"(a) : "l"(p));
    return a;
}
__device__ __forceinline__ void cp16(uint32_t sdst, const __half* src) {
    asm volatile("cp.async.cg.shared.global [%0], [%1], 16;\n" :: "r"(sdst), "l"(src));
}
__device__ __forceinline__ void ldsm4(uint32_t& r0, uint32_t& r1, uint32_t& r2, uint32_t& r3,
                                      uint32_t addr) {
    asm volatile("ldmatrix.sync.aligned.m8n8.x4.shared.b16 {%0,%1,%2,%3}, [%4];"
                 : "=r"(r0), "=r"(r1), "=r"(r2), "=r"(r3) : "r"(addr));
}

__global__ __launch_bounds__(256, 1)
void gemm_kernel(const float* __restrict__ bias, float* __restrict__ out) {
    extern __shared__ __half sm[];
    uint32_t sbu = smem_u32(sm);

    int tid = threadIdx.x;
    int m0 = blockIdx.y * BM;
    int n0 = blockIdx.x * BN;

    int warp = tid >> 5, lane = tid & 31;
    int wm = warp & 1;           // 0..1 (64 rows each)
    int wn = warp >> 1;          // 0..3 (64 cols each)
    int g  = lane >> 2;          // 0..7
    int tg = lane & 3;           // 0..3

    // ldmatrix per-lane source mapping (validated in R10)
    int a_row = (lane & 15);
    int a_kh  = (lane >> 4) * 8;
    int b_row = ((lane >> 4) ? 8 : 0) + (lane & 7);
    int b_kh  = ((lane >> 3) & 1) * 8;

    float acc[4][8][4];
    #pragma unroll
    for (int a = 0; a < 4; a++)
        #pragma unroll
        for (int b = 0; b < 8; b++)
            #pragma unroll
            for (int c = 0; c < 4; c++) acc[a][b][c] = 0.f;

    const int KT = IN_DIM / BKT;   // 128 k-tiles

    // stage loader: A 512 chunks (16B) + B 1024 chunks = 1536; 6 per thread
    #define LOAD_STAGE(stg, kt)                                               \
    {                                                                         \
        int k0 = (kt) * BKT;                                                  \
        _Pragma("unroll")                                                     \
        for (int t = 0; t < 6; t++) {                                         \
            int c = tid + t * 256;                                            \
            if (t < 2) {                                                      \
                int row = c >> 2, c4 = c & 3;                                 \
                uint32_t soff = ((stg) * A_ST + row * LDSP + c4 * 8) * 2;     \
                cp16(sbu + soff, g_y + (size_t)(m0 + row) * IN_DIM + k0 + c4 * 8); \
            } else {                                                          \
                int idx = c - 512;                                            \
                int row = idx >> 2, c4 = idx & 3;                             \
                uint32_t soff = (NSTG * A_ST + (stg) * B_ST + row * LDSP + c4 * 8) * 2; \
                cp16(sbu + soff, g_sT + (size_t)(n0 + row) * IN_DIM + k0 + c4 * 8); \
            }                                                                 \
        }                                                                     \
        asm volatile("cp.async.commit_group;\n" ::: "memory");                \
    }

    LOAD_STAGE(0, 0);
    LOAD_STAGE(1, 1);
    LOAD_STAGE(2, 2);

    for (int kt = 0; kt < KT; kt++) {
        int s = kt & (NSTG - 1);
        if (kt < KT - 2)       asm volatile("cp.async.wait_group 2;\n" ::: "memory");
        else if (kt == KT - 2) asm volatile("cp.async.wait_group 1;\n" ::: "memory");
        else                   asm volatile("cp.async.wait_group 0;\n" ::: "memory");
        __syncthreads();

        uint32_t Au = sbu + (uint32_t)(s * A_ST) * 2;
        uint32_t Bu = sbu + (uint32_t)(NSTG * A_ST + s * B_ST) * 2;

        #pragma unroll
        for (int kk = 0; kk < BKT; kk += 16) {
            uint32_t bfr[8][2];
            #pragma unroll
            for (int p = 0; p < 4; p++) {
                uint32_t addr = Bu + ((wn * 64 + p * 16 + b_row) * LDSP + kk + b_kh) * 2;
                ldsm4(bfr[2 * p][0], bfr[2 * p][1], bfr[2 * p + 1][0], bfr[2 * p + 1][1], addr);
            }
            #pragma unroll
            for (int mt = 0; mt < 4; mt++) {
                uint32_t a0, a1, a2, a3;
                uint32_t addr = Au + ((wm * 64 + mt * 16 + a_row) * LDSP + kk + a_kh) * 2;
                ldsm4(a0, a1, a2, a3, addr);
                #pragma unroll
                for (int nt = 0; nt < 8; nt++) {
                    asm volatile(
                        "mma.sync.aligned.m16n8k16.row.col.f32.f16.f16.f32 "
                        "{%0,%1,%2,%3}, {%4,%5,%6,%7}, {%8,%9}, {%0,%1,%2,%3};\n"
                        : "+f"(acc[mt][nt][0]), "+f"(acc[mt][nt][1]),
                          "+f"(acc[mt][nt][2]), "+f"(acc[mt][nt][3])
                        : "r"(a0), "r"(a1), "r"(a2), "r"(a3),
                          "r"(bfr[nt][0]), "r"(bfr[nt][1]));
                }
            }
        }
        __syncthreads();
        if (kt + 3 < KT) LOAD_STAGE((kt + 3) & (NSTG - 1), kt + 3);
    }

    // ---- epilogue: + bias, fp32 out (8B stores) ----
    #pragma unroll
    for (int mt = 0; mt < 4; mt++) {
        int r0 = m0 + wm * 64 + mt * 16 + g;
        #pragma unroll
        for (int nt = 0; nt < 8; nt++) {
            int c0 = n0 + wn * 64 + nt * 8 + 2 * tg;
            float b0v = bias[c0], b1v = bias[c0 + 1];
            float2 v0; v0.x = acc[mt][nt][0] + b0v; v0.y = acc[mt][nt][1] + b1v;
            float2 v1; v1.x = acc[mt][nt][2] + b0v; v1.y = acc[mt][nt][3] + b1v;
            *(float2*)(out + (size_t)r0 * OUT_DIM + c0)       = v0;
            *(float2*)(out + (size_t)(r0 + 8) * OUT_DIM + c0) = v1;
        }
    }
}

// ---------------- launch ----------------
extern "C" void kernel_launch(void* const* d_in, const int* in_sizes, int n_in,
                              void* d_out, int out_size) {
    const float* x    = (const float*)d_in[0];
    const float* w    = (const float*)d_in[1];
    const float* bias = (const float*)d_in[2];
    float* out = (float*)d_out;

    stats_kernel<<<IN_DIM, 256>>>(w);
    tern_kernel<<<dim3(OUT_DIM / 32, IN_DIM / 32), dim3(32, 32)>>>(w);
    scale_kernel<<<(B_DIM * (IN_DIM / 4)) / 256, 256>>>(x);

    cudaFuncSetAttribute(gemm_kernel,
                         cudaFuncAttributeMaxDynamicSharedMemorySize, SMEM_BYTES);
    gemm_kernel<<<dim3(OUT_DIM / BN, B_DIM / BM), 256, SMEM_BYTES>>>(bias, out);
}